// round 7
// baseline (speedup 1.0000x reference)
#include <cuda_runtime.h>
#include <cuda_bf16.h>
#include <math_constants.h>

// MultiLocalCosineLinear, register-resident-weights binned pipeline:
//   K0 zero hist + unit counter
//   K1 top2 per row -> pair,(a,b); rank = atomicAdd(hist[pair]) (rank stored)
//   K2 exclusive scan -> bin starts
//   K2b build work units: each bin split into chunks of <=8 rows
//   K3 scatter row ids to bin slots (start+rank, no atomics)
//   K4 one WARP per unit: weight pair held in 48 registers, streams x rows
//   out (float32): [0,B) preds, [B,3B) logits row-major (B,2)

#define NROWS   65536
#define DDIM    768
#define NCLS    100
#define NPAIRS  4950
#define F4L     6                 // 768/4/32 float4 per lane
#define CHUNK   8                 // rows per work unit
#define MAXU    (NPAIRS + NROWS / CHUNK)   // 13142 upper bound on units

__device__ int g_hist[NPAIRS];
__device__ int g_start[NPAIRS + 1];
__device__ int g_rowinfo[NROWS];   // pair | rank<<13
__device__ int g_ab[NROWS];        // a | b<<16
__device__ int g_binrows[NROWS];
__device__ int g_units[MAXU];      // pair | chunk<<16
__device__ int g_nunits;

__device__ __forceinline__ float warp_sum(float v) {
    #pragma unroll
    for (int o = 16; o; o >>= 1) v += __shfl_xor_sync(0xffffffffu, v, o);
    return v;
}
__device__ __forceinline__ float ldcs_f(const float* p) {
    float v; asm volatile("ld.global.cs.f32 %0, [%1];" : "=f"(v) : "l"(p)); return v;
}
__device__ __forceinline__ float4 ldcs_f4(const float4* p) {
    float4 v;
    asm volatile("ld.global.cs.v4.f32 {%0,%1,%2,%3}, [%4];"
                 : "=f"(v.x), "=f"(v.y), "=f"(v.z), "=f"(v.w) : "l"(p));
    return v;
}

// ---------------- K0 ----------------
__global__ void k_zero() {
    int i = blockIdx.x * blockDim.x + threadIdx.x;
    if (i < NPAIRS) g_hist[i] = 0;
    if (i == 0) g_nunits = 0;
}

// ---------------- K1: top-2 + rank ----------------
__global__ __launch_bounds__(256, 8)
void k_top2(const float* __restrict__ first_out) {
    const int row  = blockIdx.x * 8 + (threadIdx.x >> 5);
    const int lane = threadIdx.x & 31;
    if (row >= NROWS) return;

    const float* fo = first_out + (size_t)row * NCLS;
    float v1 = -CUDART_INF_F, v2 = -CUDART_INF_F;
    int   i1 = NCLS,          i2 = NCLS;
    #pragma unroll
    for (int t = 0; t < 4; ++t) {
        int c = lane + 32 * t;
        float v = (c < NCLS) ? ldcs_f(fo + c) : -CUDART_INF_F;
        if (v > v1) { v2 = v1; i2 = i1; v1 = v; i1 = c; }
        else if (v > v2) { v2 = v; i2 = c; }
    }
    #pragma unroll
    for (int off = 16; off; off >>= 1) {
        float w1 = __shfl_xor_sync(0xffffffffu, v1, off);
        int   j1 = __shfl_xor_sync(0xffffffffu, i1, off);
        float w2 = __shfl_xor_sync(0xffffffffu, v2, off);
        int   j2 = __shfl_xor_sync(0xffffffffu, i2, off);
        bool w1_best = (w1 > v1) || (w1 == v1 && j1 < i1);
        if (w1_best) {
            bool v1_second = (v1 > w2) || (v1 == w2 && i1 < j2);
            v2 = v1_second ? v1 : w2;
            i2 = v1_second ? i1 : j2;
            v1 = w1; i1 = j1;
        } else {
            bool w1_second = (w1 > v2) || (w1 == v2 && j1 < i2);
            if (w1_second) { v2 = w1; i2 = j1; }
        }
    }
    if (lane == 0) {
        const int a = min(i1, i2);
        const int b = max(i1, i2);
        const int pair = b * (b - 1) / 2 + a;
        const int rank = atomicAdd(&g_hist[pair], 1);
        g_ab[row] = a | (b << 16);
        g_rowinfo[row] = pair | (rank << 13);   // pair<8192, rank<65536
    }
}

// ---------------- K2: exclusive scan ----------------
__global__ void k_scan() {
    __shared__ int partial[1024];
    const int tid = threadIdx.x;           // 1024 threads
    const int PER = 5;                     // covers 5120 >= NPAIRS
    int base = tid * PER;
    int loc[PER];
    int sum = 0;
    #pragma unroll
    for (int i = 0; i < PER; ++i) {
        int idx = base + i;
        int v = (idx < NPAIRS) ? g_hist[idx] : 0;
        loc[i] = sum; sum += v;
    }
    partial[tid] = sum;
    __syncthreads();
    for (int off = 1; off < 1024; off <<= 1) {
        int t = (tid >= off) ? partial[tid - off] : 0;
        __syncthreads();
        partial[tid] += t;
        __syncthreads();
    }
    int chunk_start = (tid > 0) ? partial[tid - 1] : 0;
    #pragma unroll
    for (int i = 0; i < PER; ++i) {
        int idx = base + i;
        if (idx < NPAIRS) g_start[idx] = chunk_start + loc[i];
    }
    if (tid == 1023) g_start[NPAIRS] = partial[1023];
}

// ---------------- K2b: build work units ----------------
__global__ void k_units() {
    int pair = blockIdx.x * blockDim.x + threadIdx.x;
    if (pair >= NPAIRS) return;
    int cnt = g_hist[pair];
    if (cnt == 0) return;
    int nch = (cnt + CHUNK - 1) / CHUNK;
    int pos = atomicAdd(&g_nunits, nch);
    for (int c = 0; c < nch; ++c)
        g_units[pos + c] = pair | (c << 16);
}

// ---------------- K3: scatter (no atomics) ----------------
__global__ void k_scatter() {
    int row = blockIdx.x * blockDim.x + threadIdx.x;
    if (row >= NROWS) return;
    int v = g_rowinfo[row];
    int pair = v & 8191;
    int rank = v >> 13;
    g_binrows[g_start[pair] + rank] = row;
}

// ---------------- K4: warp per unit, weights in registers ----------------
__global__ __launch_bounds__(256, 2)
void k_compute(const float* __restrict__ x,
               const float* __restrict__ weights,
               const float* __restrict__ sigma,
               float* __restrict__ out)
{
    const int uid  = blockIdx.x * 8 + (threadIdx.x >> 5);
    const int lane = threadIdx.x & 31;
    if (uid >= g_nunits) return;

    const int unit  = g_units[uid];
    const int pair  = unit & 0xffff;
    const int chunk = unit >> 16;
    const int s     = g_start[pair];
    const int beg   = s + chunk * CHUNK;
    const int end   = min(g_start[pair + 1], beg + CHUNK);
    const int cnt   = end - beg;

    // weight pair -> 48 registers/lane; norms once
    const float4* w4 = (const float4*)(weights + (size_t)pair * 2 * DDIM);
    float4 w0[F4L], w1[F4L];
    float wss0 = 0.f, wss1 = 0.f;
    #pragma unroll
    for (int j = 0; j < F4L; ++j) {
        w0[j] = __ldg(w4 + lane + 32 * j);
        w1[j] = __ldg(w4 + 192 + lane + 32 * j);
    }
    #pragma unroll
    for (int j = 0; j < F4L; ++j) {
        float4 a = w0[j], b = w1[j];
        wss0 = fmaf(a.x, a.x, fmaf(a.y, a.y, fmaf(a.z, a.z, fmaf(a.w, a.w, wss0))));
        wss1 = fmaf(b.x, b.x, fmaf(b.y, b.y, fmaf(b.z, b.z, fmaf(b.w, b.w, wss1))));
    }
    wss0 = warp_sum(wss0);
    wss1 = warp_sum(wss1);
    const float sg  = __ldg(sigma + pair);
    const float sc0 = sg / fmaxf(sqrtf(wss0), 1e-12f);
    const float sc1 = sg / fmaxf(sqrtf(wss1), 1e-12f);

    for (int r = 0; r < cnt; r += 2) {
        const int rowA = g_binrows[beg + r];
        const bool hasB = (r + 1 < cnt);
        const int rowB = hasB ? g_binrows[beg + r + 1] : rowA;

        const float4* xA = (const float4*)(x + (size_t)rowA * DDIM);
        const float4* xB = (const float4*)(x + (size_t)rowB * DDIM);

        float xssA = 0.f, d0A = 0.f, d1A = 0.f;
        float xssB = 0.f, d0B = 0.f, d1B = 0.f;
        #pragma unroll
        for (int j = 0; j < F4L; ++j) {
            float4 va = ldcs_f4(xA + lane + 32 * j);
            float4 vb = ldcs_f4(xB + lane + 32 * j);
            float4 a = w0[j], b = w1[j];
            xssA = fmaf(va.x, va.x, fmaf(va.y, va.y, fmaf(va.z, va.z, fmaf(va.w, va.w, xssA))));
            d0A  = fmaf(a.x, va.x, fmaf(a.y, va.y, fmaf(a.z, va.z, fmaf(a.w, va.w, d0A))));
            d1A  = fmaf(b.x, va.x, fmaf(b.y, va.y, fmaf(b.z, va.z, fmaf(b.w, va.w, d1A))));
            xssB = fmaf(vb.x, vb.x, fmaf(vb.y, vb.y, fmaf(vb.z, vb.z, fmaf(vb.w, vb.w, xssB))));
            d0B  = fmaf(a.x, vb.x, fmaf(a.y, vb.y, fmaf(a.z, vb.z, fmaf(a.w, vb.w, d0B))));
            d1B  = fmaf(b.x, vb.x, fmaf(b.y, vb.y, fmaf(b.z, vb.z, fmaf(b.w, vb.w, d1B))));
        }
        xssA = warp_sum(xssA); d0A = warp_sum(d0A); d1A = warp_sum(d1A);
        xssB = warp_sum(xssB); d0B = warp_sum(d0B); d1B = warp_sum(d1B);

        if (lane == 0) {
            {
                const int ab = g_ab[rowA];
                const float xinv = 1.0f / fmaxf(sqrtf(xssA), 1e-12f);
                const float l0 = sc0 * d0A * xinv;
                const float l1 = sc1 * d1A * xinv;
                out[rowA] = (float)((l1 > l0) ? (ab >> 16) : (ab & 0xffff));
                out[(size_t)NROWS + 2 * (size_t)rowA + 0] = l0;
                out[(size_t)NROWS + 2 * (size_t)rowA + 1] = l1;
            }
            if (hasB) {
                const int ab = g_ab[rowB];
                const float xinv = 1.0f / fmaxf(sqrtf(xssB), 1e-12f);
                const float l0 = sc0 * d0B * xinv;
                const float l1 = sc1 * d1B * xinv;
                out[rowB] = (float)((l1 > l0) ? (ab >> 16) : (ab & 0xffff));
                out[(size_t)NROWS + 2 * (size_t)rowB + 0] = l0;
                out[(size_t)NROWS + 2 * (size_t)rowB + 1] = l1;
            }
        }
    }
}

extern "C" void kernel_launch(void* const* d_in, const int* in_sizes, int n_in,
                              void* d_out, int out_size) {
    const float* x        = (const float*)d_in[0];
    const float* first_o  = (const float*)d_in[1];
    const float* weights  = (const float*)d_in[2];
    const float* sigma    = (const float*)d_in[3];
    float* out = (float*)d_out;

    k_zero<<<(NPAIRS + 255) / 256, 256>>>();
    k_top2<<<NROWS / 8, 256>>>(first_o);
    k_scan<<<1, 1024>>>();
    k_units<<<(NPAIRS + 255) / 256, 256>>>();
    k_scatter<<<NROWS / 256, 256>>>();
    k_compute<<<(MAXU + 7) / 8, 256>>>(x, weights, sigma, out);
}

// round 8
// speedup vs baseline: 1.0940x; 1.0940x over previous
#include <cuda_runtime.h>
#include <cuda_bf16.h>
#include <math_constants.h>

// MultiLocalCosineLinear, 2-kernel latency-split:
//   K1: warp/row top-2 over first_out -> packed (pair | a<<13 | b<<20)
//   K2: warp per 2 adjacent rows; pair known up front so weight+x loads
//       issue immediately (no shuffle chain ahead of them). 2-row ILP.
//   out (float32): [0,B) preds, [B,3B) logits row-major (B,2)

#define NROWS   65536
#define DDIM    768
#define NCLS    100
#define F4L     6                 // 768/4/32 float4 per lane

__device__ int g_info[NROWS];     // pair | a<<13 | b<<20

__device__ __forceinline__ float warp_sum(float v) {
    #pragma unroll
    for (int o = 16; o; o >>= 1) v += __shfl_xor_sync(0xffffffffu, v, o);
    return v;
}
__device__ __forceinline__ float ldcs_f(const float* p) {
    float v; asm volatile("ld.global.cs.f32 %0, [%1];" : "=f"(v) : "l"(p)); return v;
}
__device__ __forceinline__ float4 ldcs_f4(const float4* p) {
    float4 v;
    asm volatile("ld.global.cs.v4.f32 {%0,%1,%2,%3}, [%4];"
                 : "=f"(v.x), "=f"(v.y), "=f"(v.z), "=f"(v.w) : "l"(p));
    return v;
}

// ---------------- K1: top-2 per row ----------------
__global__ __launch_bounds__(256, 8)
void k_top2(const float* __restrict__ first_out) {
    const int row  = blockIdx.x * 8 + (threadIdx.x >> 5);
    const int lane = threadIdx.x & 31;
    if (row >= NROWS) return;

    const float* fo = first_out + (size_t)row * NCLS;
    float v1 = -CUDART_INF_F, v2 = -CUDART_INF_F;
    int   i1 = NCLS,          i2 = NCLS;
    #pragma unroll
    for (int t = 0; t < 4; ++t) {
        int c = lane + 32 * t;
        float v = (c < NCLS) ? ldcs_f(fo + c) : -CUDART_INF_F;
        if (v > v1) { v2 = v1; i2 = i1; v1 = v; i1 = c; }
        else if (v > v2) { v2 = v; i2 = c; }
        // increasing index: equal values never displace an earlier index
    }
    #pragma unroll
    for (int off = 16; off; off >>= 1) {
        float w1 = __shfl_xor_sync(0xffffffffu, v1, off);
        int   j1 = __shfl_xor_sync(0xffffffffu, i1, off);
        float w2 = __shfl_xor_sync(0xffffffffu, v2, off);
        int   j2 = __shfl_xor_sync(0xffffffffu, i2, off);
        bool w1_best = (w1 > v1) || (w1 == v1 && j1 < i1);
        if (w1_best) {
            bool v1_second = (v1 > w2) || (v1 == w2 && i1 < j2);
            v2 = v1_second ? v1 : w2;
            i2 = v1_second ? i1 : j2;
            v1 = w1; i1 = j1;
        } else {
            bool w1_second = (w1 > v2) || (w1 == v2 && j1 < i2);
            if (w1_second) { v2 = w1; i2 = j1; }
        }
    }
    if (lane == 0) {
        const int a = min(i1, i2);
        const int b = max(i1, i2);
        const int pair = b * (b - 1) / 2 + a;      // < 4950, fits 13 bits
        g_info[row] = pair | (a << 13) | (b << 20);
    }
}

// ---------------- K2: warp per 2 rows, full-MLP compute ----------------
__global__ __launch_bounds__(256, 2)
void k_compute(const float* __restrict__ x,
               const float* __restrict__ weights,
               const float* __restrict__ sigma,
               float* __restrict__ out)
{
    const int warp = blockIdx.x * 8 + (threadIdx.x >> 5);
    const int lane = threadIdx.x & 31;
    const int rowA = 2 * warp;
    const int rowB = rowA + 1;
    if (rowA >= NROWS) return;

    const int infoA = g_info[rowA];
    const int infoB = g_info[rowB];
    const int pairA = infoA & 8191;
    const int pairB = infoB & 8191;

    // x rows -> registers (streaming, evict-first), ||x||^2 on the fly
    const float4* xA = (const float4*)(x + (size_t)rowA * DDIM);
    const float4* xB = (const float4*)(x + (size_t)rowB * DDIM);
    float4 vA[F4L], vB[F4L];
    #pragma unroll
    for (int j = 0; j < F4L; ++j) vA[j] = ldcs_f4(xA + lane + 32 * j);
    #pragma unroll
    for (int j = 0; j < F4L; ++j) vB[j] = ldcs_f4(xB + lane + 32 * j);

    const float4* wA = (const float4*)(weights + (size_t)pairA * 2 * DDIM);
    const float4* wB = (const float4*)(weights + (size_t)pairB * 2 * DDIM);

    float xssA = 0.f, xssB = 0.f;
    #pragma unroll
    for (int j = 0; j < F4L; ++j) {
        float4 a = vA[j], b = vB[j];
        xssA = fmaf(a.x, a.x, fmaf(a.y, a.y, fmaf(a.z, a.z, fmaf(a.w, a.w, xssA))));
        xssB = fmaf(b.x, b.x, fmaf(b.y, b.y, fmaf(b.z, b.z, fmaf(b.w, b.w, xssB))));
    }

    // dots + weight norms: 4 weight rows streamed (default caching: L2-resident)
    float d0A = 0.f, d1A = 0.f, s0A = 0.f, s1A = 0.f;
    float d0B = 0.f, d1B = 0.f, s0B = 0.f, s1B = 0.f;
    #pragma unroll
    for (int j = 0; j < F4L; ++j) {
        const int idx = lane + 32 * j;
        float4 w0a = __ldg(wA + idx);
        float4 w1a = __ldg(wA + 192 + idx);
        float4 w0b = __ldg(wB + idx);
        float4 w1b = __ldg(wB + 192 + idx);
        float4 a = vA[j], b = vB[j];
        d0A = fmaf(w0a.x, a.x, fmaf(w0a.y, a.y, fmaf(w0a.z, a.z, fmaf(w0a.w, a.w, d0A))));
        s0A = fmaf(w0a.x, w0a.x, fmaf(w0a.y, w0a.y, fmaf(w0a.z, w0a.z, fmaf(w0a.w, w0a.w, s0A))));
        d1A = fmaf(w1a.x, a.x, fmaf(w1a.y, a.y, fmaf(w1a.z, a.z, fmaf(w1a.w, a.w, d1A))));
        s1A = fmaf(w1a.x, w1a.x, fmaf(w1a.y, w1a.y, fmaf(w1a.z, w1a.z, fmaf(w1a.w, w1a.w, s1A))));
        d0B = fmaf(w0b.x, b.x, fmaf(w0b.y, b.y, fmaf(w0b.z, b.z, fmaf(w0b.w, b.w, d0B))));
        s0B = fmaf(w0b.x, w0b.x, fmaf(w0b.y, w0b.y, fmaf(w0b.z, w0b.z, fmaf(w0b.w, w0b.w, s0B))));
        d1B = fmaf(w1b.x, b.x, fmaf(w1b.y, b.y, fmaf(w1b.z, b.z, fmaf(w1b.w, b.w, d1B))));
        s1B = fmaf(w1b.x, w1b.x, fmaf(w1b.y, w1b.y, fmaf(w1b.z, w1b.z, fmaf(w1b.w, w1b.w, s1B))));
    }

    xssA = warp_sum(xssA); d0A = warp_sum(d0A); d1A = warp_sum(d1A);
    s0A  = warp_sum(s0A);  s1A = warp_sum(s1A);
    xssB = warp_sum(xssB); d0B = warp_sum(d0B); d1B = warp_sum(d1B);
    s0B  = warp_sum(s0B);  s1B = warp_sum(s1B);

    if (lane == 0) {
        const float sgA = __ldg(sigma + pairA);
        const float sgB = __ldg(sigma + pairB);
        const float xiA = 1.0f / fmaxf(sqrtf(xssA), 1e-12f);
        const float xiB = 1.0f / fmaxf(sqrtf(xssB), 1e-12f);
        const float l0A = sgA * d0A * xiA / fmaxf(sqrtf(s0A), 1e-12f);
        const float l1A = sgA * d1A * xiA / fmaxf(sqrtf(s1A), 1e-12f);
        const float l0B = sgB * d0B * xiB / fmaxf(sqrtf(s0B), 1e-12f);
        const float l1B = sgB * d1B * xiB / fmaxf(sqrtf(s1B), 1e-12f);

        const int aA = (infoA >> 13) & 127, bA = infoA >> 20;
        const int aB = (infoB >> 13) & 127, bB = infoB >> 20;
        const float predA = (float)((l1A > l0A) ? bA : aA);   // argmax, first on tie
        const float predB = (float)((l1B > l0B) ? bB : aB);

        *(float2*)(out + rowA) = make_float2(predA, predB);
        *(float4*)(out + (size_t)NROWS + 2 * (size_t)rowA) =
            make_float4(l0A, l1A, l0B, l1B);
    }
}

extern "C" void kernel_launch(void* const* d_in, const int* in_sizes, int n_in,
                              void* d_out, int out_size) {
    const float* x        = (const float*)d_in[0];
    const float* first_o  = (const float*)d_in[1];
    const float* weights  = (const float*)d_in[2];
    const float* sigma    = (const float*)d_in[3];
    float* out = (float*)d_out;

    k_top2<<<NROWS / 8, 256>>>(first_o);
    k_compute<<<NROWS / 16, 256>>>(x, weights, sigma, out);
}